// round 7
// baseline (speedup 1.0000x reference)
#include <cuda_runtime.h>
#include <cuda_fp16.h>
#include <cstdint>
#include <cstddef>

// ---------------------------------------------------------------------------
// Problem constants
// ---------------------------------------------------------------------------
#define VOCAB 50257
#define DMODEL 768
#define NEXP 4
#define RRANK 32
#define BATCH 4
#define SEQ 512
#define NROWS (BATCH * SEQ)   // 2048

// ---------------------------------------------------------------------------
// Scratch (static device buffers; no cudaMalloc allowed)
// ---------------------------------------------------------------------------
__device__ __align__(256) float  g_x[NROWS * DMODEL];
__device__ __align__(256) __half g_h16[NROWS * DMODEL];
__device__ __align__(256) float  g_P[NROWS * NEXP * RRANK];
__device__ __align__(256) float  g_C[NROWS * RRANK];
__device__ __align__(256) int    g_E[NROWS];
__device__ __align__(256) __half g_Wh[(size_t)VOCAB * DMODEL];  // fp16 W_emb

__device__ __forceinline__ uint32_t smem_u32(const void* p) {
    uint32_t a;
    asm("{ .reg .u64 t; cvta.to.shared.u64 t, %1; cvt.u32.u64 %0, t; }"
        : "=r"(a) : "l"(p));
    return a;
}

__device__ __forceinline__ void cpasync16(uint32_t dst, const void* src, int szbytes) {
    asm volatile("cp.async.cg.shared.global [%0], [%1], 16, %2;"
                 :: "r"(dst), "l"(src), "r"(szbytes));
}
#define CP_COMMIT() asm volatile("cp.async.commit_group;" ::: "memory")
#define CP_WAIT2()  asm volatile("cp.async.wait_group 2;" ::: "memory")

// ---------------------------------------------------------------------------
// Kernel 0: convert W_emb (fp32) -> fp16. Each thread does 8 elements.
// ---------------------------------------------------------------------------
__global__ __launch_bounds__(256) void k_round(const float* __restrict__ W) {
    const size_t g = (size_t)blockIdx.x * 256 + threadIdx.x;
    const size_t ng = ((size_t)VOCAB * DMODEL) / 8;
    if (g >= ng) return;
    const float4 v0 = *((const float4*)W + g * 2);
    const float4 v1 = *((const float4*)W + g * 2 + 1);
    __half2 h[4];
    h[0] = __floats2half2_rn(v0.x, v0.y);
    h[1] = __floats2half2_rn(v0.z, v0.w);
    h[2] = __floats2half2_rn(v1.x, v1.y);
    h[3] = __floats2half2_rn(v1.z, v1.w);
    *((uint4*)g_Wh + g) = *(uint4*)h;
}

// ---------------------------------------------------------------------------
// Kernel 1: embedding gather + routing scores + input projection (all experts)
// ---------------------------------------------------------------------------
__global__ __launch_bounds__(160) void k_embed_route(
    const int* __restrict__ idx, const float* __restrict__ Wemb,
    const float* __restrict__ G, const float* __restrict__ Win) {
    __shared__ float xs[8][DMODEL];
    __shared__ float ssc[8][NEXP];
    __shared__ int tok[8];
    const int tid = threadIdx.x;
    const int row0 = blockIdx.x * 8;

    if (tid < 8) tok[tid] = idx[row0 + tid];
    __syncthreads();
    for (int i = tid; i < 8 * DMODEL; i += 160) {
        int rr = i / DMODEL, d = i - rr * DMODEL;
        float v = Wemb[(size_t)tok[rr] * DMODEL + d];
        xs[rr][d] = v;
        g_x[(size_t)(row0 + rr) * DMODEL + d] = v;
    }
    __syncthreads();

    const int j = tid;
    if (j < 132) {
        float acc[8];
#pragma unroll
        for (int rr = 0; rr < 8; rr++) acc[rr] = 0.0f;
        const float* wp;
        int stride;
        if (j < 128) { int e = j >> 5, r = j & 31; wp = Win + (size_t)e * DMODEL * RRANK + r; stride = RRANK; }
        else         { wp = G + (size_t)(j - 128) * DMODEL; stride = 1; }
        for (int d = 0; d < DMODEL; d += 4) {
            float w0 = wp[(size_t)d * stride];
            float w1 = wp[(size_t)(d + 1) * stride];
            float w2 = wp[(size_t)(d + 2) * stride];
            float w3 = wp[(size_t)(d + 3) * stride];
#pragma unroll
            for (int rr = 0; rr < 8; rr++) {
                float4 xv = *(const float4*)&xs[rr][d];
                acc[rr] = fmaf(xv.x, w0, acc[rr]);
                acc[rr] = fmaf(xv.y, w1, acc[rr]);
                acc[rr] = fmaf(xv.z, w2, acc[rr]);
                acc[rr] = fmaf(xv.w, w3, acc[rr]);
            }
        }
        if (j < 128) {
#pragma unroll
            for (int rr = 0; rr < 8; rr++)
                g_P[(size_t)(row0 + rr) * (NEXP * RRANK) + j] = acc[rr];
        } else {
#pragma unroll
            for (int rr = 0; rr < 8; rr++) ssc[rr][j - 128] = acc[rr];
        }
    }
    __syncthreads();
    if (tid < 8) {
        float best = ssc[tid][0];
        int be = 0;
#pragma unroll
        for (int e = 1; e < NEXP; e++)
            if (ssc[tid][e] > best) { best = ssc[tid][e]; be = e; }
        g_E[row0 + tid] = be;
    }
}

// ---------------------------------------------------------------------------
// Kernel 2: sequential recurrence over time (1 block, 1 warp per batch).
// ---------------------------------------------------------------------------
#define STEP_CASE(ST, WR) {                                                    \
    float a0 = 0.f, a1 = 0.f, a2 = 0.f, a3 = 0.f;                              \
    _Pragma("unroll")                                                          \
    for (int k = 0; k < 8; k++) {                                              \
        a0 = fmaf(__shfl_sync(0xffffffffu, ST, k     ), WR[k     ], a0);       \
        a1 = fmaf(__shfl_sync(0xffffffffu, ST, k +  8), WR[k +  8], a1);       \
        a2 = fmaf(__shfl_sync(0xffffffffu, ST, k + 16), WR[k + 16], a2);       \
        a3 = fmaf(__shfl_sync(0xffffffffu, ST, k + 24), WR[k + 24], a3);       \
    }                                                                          \
    cand = tanhf(p_cur + ((a0 + a1) + (a2 + a3)));                             \
    ST = cand; }

__global__ __launch_bounds__(128, 1) void k_scan(const float* __restrict__ Wrec) {
    const int tid = threadIdx.x;
    const int b = tid >> 5;
    const int o = tid & 31;

    float wr0[32], wr1[32], wr2[32], wr3[32];
#pragma unroll
    for (int k = 0; k < 32; k++) {
        wr0[k] = Wrec[          k * 32 + o];
        wr1[k] = Wrec[1024 +    k * 32 + o];
        wr2[k] = Wrec[2048 +    k * 32 + o];
        wr3[k] = Wrec[3072 +    k * 32 + o];
    }
    float st0 = 0.f, st1 = 0.f, st2 = 0.f, st3 = 0.f;

    const int base = b * SEQ;
    int   e_cur = g_E[base];
    int   e_nxt = g_E[base + 1];
    float p_cur = g_P[(size_t)base * 128 + e_cur * 32 + o];

    for (int t = 0; t < SEQ; t++) {
        float p_nxt = 0.f;
        int   e_nn = 0;
        if (t + 1 < SEQ) p_nxt = g_P[(size_t)(base + t + 1) * 128 + e_nxt * 32 + o];
        if (t + 2 < SEQ) e_nn = g_E[base + t + 2];

        float cand;
        switch (e_cur) {
            case 0: STEP_CASE(st0, wr0); break;
            case 1: STEP_CASE(st1, wr1); break;
            case 2: STEP_CASE(st2, wr2); break;
            default: STEP_CASE(st3, wr3); break;
        }
        g_C[(size_t)(base + t) * 32 + o] = cand;

        p_cur = p_nxt; e_cur = e_nxt; e_nxt = e_nn;
    }
}

// ---------------------------------------------------------------------------
// Kernel 3: output projection + residual + LayerNorm -> fp16 h
// ---------------------------------------------------------------------------
__global__ __launch_bounds__(256) void k_outln(
    const float* __restrict__ Wout, const float* __restrict__ gamma,
    const float* __restrict__ beta) {
    __shared__ float csh[32];
    __shared__ float rs[8], rs2[8];
    const int row = blockIdx.x;
    const int tid = threadIdx.x;
    if (tid < 32) csh[tid] = g_C[(size_t)row * 32 + tid];
    const int e = g_E[row];
    __syncthreads();

    const float* wb = Wout + (size_t)e * RRANK * DMODEL;
    float y[3];
    float s = 0.f, s2 = 0.f;
#pragma unroll
    for (int ii = 0; ii < 3; ii++) {
        int d = tid + ii * 256;
        float acc = g_x[(size_t)row * DMODEL + d];
#pragma unroll
        for (int r = 0; r < 32; r++)
            acc = fmaf(csh[r], wb[r * DMODEL + d], acc);
        y[ii] = acc;
        s += acc;
        s2 = fmaf(acc, acc, s2);
    }
#pragma unroll
    for (int off = 16; off; off >>= 1) {
        s  += __shfl_xor_sync(0xffffffffu, s, off);
        s2 += __shfl_xor_sync(0xffffffffu, s2, off);
    }
    if ((tid & 31) == 0) { rs[tid >> 5] = s; rs2[tid >> 5] = s2; }
    __syncthreads();
    float S = 0.f, S2 = 0.f;
#pragma unroll
    for (int w = 0; w < 8; w++) { S += rs[w]; S2 += rs2[w]; }
    const float mean = S * (1.0f / DMODEL);
    const float var = S2 * (1.0f / DMODEL) - mean * mean;
    const float inv = rsqrtf(var + 1e-5f);
#pragma unroll
    for (int ii = 0; ii < 3; ii++) {
        int d = tid + ii * 256;
        float hv = (y[ii] - mean) * inv * gamma[d] + beta[d];
        g_h16[(size_t)row * DMODEL + d] = __float2half_rn(hv);
    }
}

// ---------------------------------------------------------------------------
// Kernel 4: logits = h @ W_emb^T, fp16 mma.sync.m16n8k16 (fp32 accumulate).
//   CTA 128x256, 512 threads / 16 warps (2m x 8n), warp tile 64x32
//   => 4 warps per SMSP to cover barrier/cp.async shadows.
//   K chunk 64, 3-stage cp.async. Row stride 72 halves: conflict-free LDS.
// ---------------------------------------------------------------------------
#define GTM 128
#define GTN 256
#define GKB 64
#define NKB (DMODEL / GKB)          // 12
#define ASTRH 72                    // halves per row
#define A_STAGE_H (GTM * ASTRH)     // 9216 halves
#define B_STAGE_H (GTN * ASTRH)     // 18432 halves
#define NSTAGE 3
#define BOFFH (NSTAGE * A_STAGE_H)
#define GEMM_SMEM (NSTAGE * (A_STAGE_H + B_STAGE_H) * 2)   // 165,888 B

__device__ __forceinline__ void mma_f16_16n8k16(
    float* c, const uint32_t* a, const uint32_t* b) {
    asm volatile(
        "mma.sync.aligned.m16n8k16.row.col.f32.f16.f16.f32 "
        "{%0,%1,%2,%3}, {%4,%5,%6,%7}, {%8,%9}, {%0,%1,%2,%3};"
        : "+f"(c[0]), "+f"(c[1]), "+f"(c[2]), "+f"(c[3])
        : "r"(a[0]), "r"(a[1]), "r"(a[2]), "r"(a[3]), "r"(b[0]), "r"(b[1]));
}

__global__ __launch_bounds__(512, 1) void k_gemm(
    const __half* __restrict__ A, const __half* __restrict__ Bw,
    float* __restrict__ C) {
    extern __shared__ __half smh[];
    const uint32_t smb = smem_u32(smh);

    const int tid = threadIdx.x;
    const int wid = tid >> 5, lane = tid & 31;
    const int wm = wid & 1, wn = wid >> 1;       // 2(m) x 8(n)
    const int lr = lane >> 2, lc = lane & 3;
    const int m0 = blockIdx.x * GTM;
    const int n0 = blockIdx.y * GTN;

    float acc[4][4][4];
#pragma unroll
    for (int mf = 0; mf < 4; mf++)
#pragma unroll
        for (int nf = 0; nf < 4; nf++)
#pragma unroll
            for (int q = 0; q < 4; q++) acc[mf][nf][q] = 0.0f;

    // per-stage copy: rows have 8 chunks of 8 halves (16B).
    // A: 128 rows -> 1024 chunks (2/thread); B: 256 rows -> 2048 (4/thread)
    auto issue = [&](int kb, int s) {
        const uint32_t abase = smb + (uint32_t)(s * A_STAGE_H) * 2;
#pragma unroll
        for (int i = 0; i < 2; i++) {
            int j = tid + i * 512;
            int r = j >> 3, c8 = j & 7;
            cpasync16(abase + (uint32_t)(r * ASTRH + c8 * 8) * 2,
                      A + (size_t)(m0 + r) * DMODEL + kb * GKB + c8 * 8, 16);
        }
        const uint32_t bbase = smb + (uint32_t)(BOFFH + s * B_STAGE_H) * 2;
#pragma unroll
        for (int i = 0; i < 4; i++) {
            int j = tid + i * 512;
            int r = j >> 3, c8 = j & 7;
            int rn = n0 + r;
            int ok = (rn < VOCAB);
            int rsrc = ok ? rn : (VOCAB - 1);
            cpasync16(bbase + (uint32_t)(r * ASTRH + c8 * 8) * 2,
                      Bw + (size_t)rsrc * DMODEL + kb * GKB + c8 * 8, ok ? 16 : 0);
        }
        CP_COMMIT();
    };

    issue(0, 0);
    issue(1, 1);

    for (int kb = 0; kb < NKB; kb++) {
        const int s = kb % NSTAGE;
        if (kb + 2 < NKB) issue(kb + 2, (kb + 2) % NSTAGE); else CP_COMMIT();
        CP_WAIT2();        // 3 groups outstanding -> group kb complete
        __syncthreads();

        const __half* as = smh + s * A_STAGE_H + (wm * 64 + lr) * ASTRH + 2 * lc;
        const __half* bs = smh + BOFFH + s * B_STAGE_H + (wn * 32 + lr) * ASTRH + 2 * lc;
#pragma unroll
        for (int sl = 0; sl < 4; sl++) {       // 4 x k16 slices
            const int ko = sl * 16;
            uint32_t af[4][4], bf[4][2];
#pragma unroll
            for (int mf = 0; mf < 4; mf++) {
                const __half* ap = as + mf * 16 * ASTRH + ko;
                af[mf][0] = *(const uint32_t*)(ap);
                af[mf][1] = *(const uint32_t*)(ap + 8 * ASTRH);
                af[mf][2] = *(const uint32_t*)(ap + 8);
                af[mf][3] = *(const uint32_t*)(ap + 8 * ASTRH + 8);
            }
#pragma unroll
            for (int nf = 0; nf < 4; nf++) {
                const __half* bp = bs + nf * 8 * ASTRH + ko;
                bf[nf][0] = *(const uint32_t*)(bp);
                bf[nf][1] = *(const uint32_t*)(bp + 8);
            }
#pragma unroll
            for (int mf = 0; mf < 4; mf++)
#pragma unroll
                for (int nf = 0; nf < 4; nf++)
                    mma_f16_16n8k16(acc[mf][nf], af[mf], bf[nf]);
        }
        __syncthreads();   // all warps done reading stage s
    }

    // epilogue: scalar 4B stores (VOCAB odd => no 8B alignment guarantee)
#pragma unroll
    for (int mf = 0; mf < 4; mf++) {
        const int row = m0 + wm * 64 + mf * 16 + lr;
#pragma unroll
        for (int nf = 0; nf < 4; nf++) {
            const int col = n0 + wn * 32 + nf * 8 + 2 * lc;
            float* c0p = C + (size_t)row * VOCAB + col;
            float* c2p = C + (size_t)(row + 8) * VOCAB + col;
            if (col + 1 < VOCAB) {
                c0p[0] = acc[mf][nf][0];
                c0p[1] = acc[mf][nf][1];
                c2p[0] = acc[mf][nf][2];
                c2p[1] = acc[mf][nf][3];
            } else if (col < VOCAB) {
                c0p[0] = acc[mf][nf][0];
                c2p[0] = acc[mf][nf][2];
            }
        }
    }
}

// ---------------------------------------------------------------------------
// Launch
// ---------------------------------------------------------------------------
extern "C" void kernel_launch(void* const* d_in, const int* in_sizes, int n_in,
                              void* d_out, int out_size) {
    const int*   idx   = (const int*)d_in[0];
    const float* Wemb  = (const float*)d_in[1];
    const float* G     = (const float*)d_in[2];
    const float* Win   = (const float*)d_in[3];
    const float* Wrec  = (const float*)d_in[4];
    const float* Wout  = (const float*)d_in[5];
    const float* gamma = (const float*)d_in[6];
    const float* beta  = (const float*)d_in[7];
    float* out = (float*)d_out;

    cudaFuncSetAttribute(k_gemm, cudaFuncAttributeMaxDynamicSharedMemorySize,
                         GEMM_SMEM);

    const size_t ng = ((size_t)VOCAB * DMODEL) / 8;
    k_round<<<(unsigned)((ng + 255) / 256), 256>>>(Wemb);
    k_embed_route<<<NROWS / 8, 160>>>(idx, Wemb, G, Win);
    k_scan<<<1, 128>>>(Wrec);
    k_outln<<<NROWS, 256>>>(Wout, gamma, beta);

    __half *hptr, *wtptr;
    cudaGetSymbolAddress((void**)&hptr, g_h16);
    cudaGetSymbolAddress((void**)&wtptr, g_Wh);
    dim3 grid(NROWS / GTM, (VOCAB + GTN - 1) / GTN);   // (16, 197)
    k_gemm<<<grid, 512, GEMM_SMEM>>>(hptr, wtptr, out);
}

// round 8
// speedup vs baseline: 1.0700x; 1.0700x over previous
#include <cuda_runtime.h>
#include <cuda_fp16.h>
#include <cstdint>
#include <cstddef>

// ---------------------------------------------------------------------------
// Problem constants
// ---------------------------------------------------------------------------
#define VOCAB 50257
#define DMODEL 768
#define NEXP 4
#define RRANK 32
#define BATCH 4
#define SEQ 512
#define NROWS (BATCH * SEQ)   // 2048

// ---------------------------------------------------------------------------
// Scratch (static device buffers; no cudaMalloc allowed)
// ---------------------------------------------------------------------------
__device__ __align__(256) float  g_x[NROWS * DMODEL];
__device__ __align__(256) __half g_h16[NROWS * DMODEL];
__device__ __align__(256) float  g_P[NROWS * NEXP * RRANK];
__device__ __align__(256) float  g_C[NROWS * RRANK];
__device__ __align__(256) int    g_E[NROWS];
__device__ __align__(256) __half g_Wh[(size_t)VOCAB * DMODEL];  // fp16 W_emb

__device__ __forceinline__ uint32_t smem_u32(const void* p) {
    uint32_t a;
    asm("{ .reg .u64 t; cvta.to.shared.u64 t, %1; cvt.u32.u64 %0, t; }"
        : "=r"(a) : "l"(p));
    return a;
}

__device__ __forceinline__ void cpasync16(uint32_t dst, const void* src, int szbytes) {
    asm volatile("cp.async.cg.shared.global [%0], [%1], 16, %2;"
                 :: "r"(dst), "l"(src), "r"(szbytes));
}
#define CP_COMMIT() asm volatile("cp.async.commit_group;" ::: "memory")
#define CP_WAIT3()  asm volatile("cp.async.wait_group 3;" ::: "memory")

__device__ __forceinline__ void ldsm_x4(uint32_t* r, uint32_t addr) {
    asm volatile("ldmatrix.sync.aligned.m8n8.x4.shared.b16 {%0,%1,%2,%3}, [%4];"
                 : "=r"(r[0]), "=r"(r[1]), "=r"(r[2]), "=r"(r[3]) : "r"(addr));
}

// ---------------------------------------------------------------------------
// Kernel 0: convert W_emb (fp32) -> fp16. Each thread does 8 elements.
// ---------------------------------------------------------------------------
__global__ __launch_bounds__(256) void k_round(const float* __restrict__ W) {
    const size_t g = (size_t)blockIdx.x * 256 + threadIdx.x;
    const size_t ng = ((size_t)VOCAB * DMODEL) / 8;
    if (g >= ng) return;
    const float4 v0 = *((const float4*)W + g * 2);
    const float4 v1 = *((const float4*)W + g * 2 + 1);
    __half2 h[4];
    h[0] = __floats2half2_rn(v0.x, v0.y);
    h[1] = __floats2half2_rn(v0.z, v0.w);
    h[2] = __floats2half2_rn(v1.x, v1.y);
    h[3] = __floats2half2_rn(v1.z, v1.w);
    *((uint4*)g_Wh + g) = *(uint4*)h;
}

// ---------------------------------------------------------------------------
// Kernel 1: embedding gather + routing scores + input projection (all experts)
// ---------------------------------------------------------------------------
__global__ __launch_bounds__(160) void k_embed_route(
    const int* __restrict__ idx, const float* __restrict__ Wemb,
    const float* __restrict__ G, const float* __restrict__ Win) {
    __shared__ float xs[8][DMODEL];
    __shared__ float ssc[8][NEXP];
    __shared__ int tok[8];
    const int tid = threadIdx.x;
    const int row0 = blockIdx.x * 8;

    if (tid < 8) tok[tid] = idx[row0 + tid];
    __syncthreads();
    for (int i = tid; i < 8 * DMODEL; i += 160) {
        int rr = i / DMODEL, d = i - rr * DMODEL;
        float v = Wemb[(size_t)tok[rr] * DMODEL + d];
        xs[rr][d] = v;
        g_x[(size_t)(row0 + rr) * DMODEL + d] = v;
    }
    __syncthreads();

    const int j = tid;
    if (j < 132) {
        float acc[8];
#pragma unroll
        for (int rr = 0; rr < 8; rr++) acc[rr] = 0.0f;
        const float* wp;
        int stride;
        if (j < 128) { int e = j >> 5, r = j & 31; wp = Win + (size_t)e * DMODEL * RRANK + r; stride = RRANK; }
        else         { wp = G + (size_t)(j - 128) * DMODEL; stride = 1; }
        for (int d = 0; d < DMODEL; d += 4) {
            float w0 = wp[(size_t)d * stride];
            float w1 = wp[(size_t)(d + 1) * stride];
            float w2 = wp[(size_t)(d + 2) * stride];
            float w3 = wp[(size_t)(d + 3) * stride];
#pragma unroll
            for (int rr = 0; rr < 8; rr++) {
                float4 xv = *(const float4*)&xs[rr][d];
                acc[rr] = fmaf(xv.x, w0, acc[rr]);
                acc[rr] = fmaf(xv.y, w1, acc[rr]);
                acc[rr] = fmaf(xv.z, w2, acc[rr]);
                acc[rr] = fmaf(xv.w, w3, acc[rr]);
            }
        }
        if (j < 128) {
#pragma unroll
            for (int rr = 0; rr < 8; rr++)
                g_P[(size_t)(row0 + rr) * (NEXP * RRANK) + j] = acc[rr];
        } else {
#pragma unroll
            for (int rr = 0; rr < 8; rr++) ssc[rr][j - 128] = acc[rr];
        }
    }
    __syncthreads();
    if (tid < 8) {
        float best = ssc[tid][0];
        int be = 0;
#pragma unroll
        for (int e = 1; e < NEXP; e++)
            if (ssc[tid][e] > best) { best = ssc[tid][e]; be = e; }
        g_E[row0 + tid] = be;
    }
}

// ---------------------------------------------------------------------------
// Kernel 2: sequential recurrence over time (1 block, 1 warp per batch).
// ---------------------------------------------------------------------------
#define STEP_CASE(ST, WR) {                                                    \
    float a0 = 0.f, a1 = 0.f, a2 = 0.f, a3 = 0.f;                              \
    _Pragma("unroll")                                                          \
    for (int k = 0; k < 8; k++) {                                              \
        a0 = fmaf(__shfl_sync(0xffffffffu, ST, k     ), WR[k     ], a0);       \
        a1 = fmaf(__shfl_sync(0xffffffffu, ST, k +  8), WR[k +  8], a1);       \
        a2 = fmaf(__shfl_sync(0xffffffffu, ST, k + 16), WR[k + 16], a2);       \
        a3 = fmaf(__shfl_sync(0xffffffffu, ST, k + 24), WR[k + 24], a3);       \
    }                                                                          \
    cand = tanhf(p_cur + ((a0 + a1) + (a2 + a3)));                             \
    ST = cand; }

__global__ __launch_bounds__(128, 1) void k_scan(const float* __restrict__ Wrec) {
    const int tid = threadIdx.x;
    const int b = tid >> 5;
    const int o = tid & 31;

    float wr0[32], wr1[32], wr2[32], wr3[32];
#pragma unroll
    for (int k = 0; k < 32; k++) {
        wr0[k] = Wrec[          k * 32 + o];
        wr1[k] = Wrec[1024 +    k * 32 + o];
        wr2[k] = Wrec[2048 +    k * 32 + o];
        wr3[k] = Wrec[3072 +    k * 32 + o];
    }
    float st0 = 0.f, st1 = 0.f, st2 = 0.f, st3 = 0.f;

    const int base = b * SEQ;
    int   e_cur = g_E[base];
    int   e_nxt = g_E[base + 1];
    float p_cur = g_P[(size_t)base * 128 + e_cur * 32 + o];

    for (int t = 0; t < SEQ; t++) {
        float p_nxt = 0.f;
        int   e_nn = 0;
        if (t + 1 < SEQ) p_nxt = g_P[(size_t)(base + t + 1) * 128 + e_nxt * 32 + o];
        if (t + 2 < SEQ) e_nn = g_E[base + t + 2];

        float cand;
        switch (e_cur) {
            case 0: STEP_CASE(st0, wr0); break;
            case 1: STEP_CASE(st1, wr1); break;
            case 2: STEP_CASE(st2, wr2); break;
            default: STEP_CASE(st3, wr3); break;
        }
        g_C[(size_t)(base + t) * 32 + o] = cand;

        p_cur = p_nxt; e_cur = e_nxt; e_nxt = e_nn;
    }
}

// ---------------------------------------------------------------------------
// Kernel 3: output projection + residual + LayerNorm -> fp16 h
// ---------------------------------------------------------------------------
__global__ __launch_bounds__(256) void k_outln(
    const float* __restrict__ Wout, const float* __restrict__ gamma,
    const float* __restrict__ beta) {
    __shared__ float csh[32];
    __shared__ float rs[8], rs2[8];
    const int row = blockIdx.x;
    const int tid = threadIdx.x;
    if (tid < 32) csh[tid] = g_C[(size_t)row * 32 + tid];
    const int e = g_E[row];
    __syncthreads();

    const float* wb = Wout + (size_t)e * RRANK * DMODEL;
    float y[3];
    float s = 0.f, s2 = 0.f;
#pragma unroll
    for (int ii = 0; ii < 3; ii++) {
        int d = tid + ii * 256;
        float acc = g_x[(size_t)row * DMODEL + d];
#pragma unroll
        for (int r = 0; r < 32; r++)
            acc = fmaf(csh[r], wb[r * DMODEL + d], acc);
        y[ii] = acc;
        s += acc;
        s2 = fmaf(acc, acc, s2);
    }
#pragma unroll
    for (int off = 16; off; off >>= 1) {
        s  += __shfl_xor_sync(0xffffffffu, s, off);
        s2 += __shfl_xor_sync(0xffffffffu, s2, off);
    }
    if ((tid & 31) == 0) { rs[tid >> 5] = s; rs2[tid >> 5] = s2; }
    __syncthreads();
    float S = 0.f, S2 = 0.f;
#pragma unroll
    for (int w = 0; w < 8; w++) { S += rs[w]; S2 += rs2[w]; }
    const float mean = S * (1.0f / DMODEL);
    const float var = S2 * (1.0f / DMODEL) - mean * mean;
    const float inv = rsqrtf(var + 1e-5f);
#pragma unroll
    for (int ii = 0; ii < 3; ii++) {
        int d = tid + ii * 256;
        float hv = (y[ii] - mean) * inv * gamma[d] + beta[d];
        g_h16[(size_t)row * DMODEL + d] = __float2half_rn(hv);
    }
}

// ---------------------------------------------------------------------------
// Kernel 4: logits = h @ W_emb^T, fp16 mma.sync.m16n8k16 (fp32 accumulate).
//   CTA 128x256, 256 threads / 8 warps (2m x 4n), warp tile 64x64.
//   Fragment loads via ldmatrix.x4 (A: 4/slice, B: 4/slice covering 2 nf).
//   K chunk 64, 4-stage cp.async (221KB smem). 144B row stride: LDSM rows
//   land on distinct bank groups (36i mod 32 = 4i) -> conflict-free.
// ---------------------------------------------------------------------------
#define GTM 128
#define GTN 256
#define GKB 64
#define NKB (DMODEL / GKB)          // 12
#define ASTRH 72                    // halves per row
#define A_STAGE_H (GTM * ASTRH)     // 9216 halves
#define B_STAGE_H (GTN * ASTRH)     // 18432 halves
#define NSTAGE 4
#define BOFFH (NSTAGE * A_STAGE_H)
#define GEMM_SMEM (NSTAGE * (A_STAGE_H + B_STAGE_H) * 2)   // 221,184 B

__device__ __forceinline__ void mma_f16_16n8k16(
    float* c, const uint32_t* a, const uint32_t* b) {
    asm volatile(
        "mma.sync.aligned.m16n8k16.row.col.f32.f16.f16.f32 "
        "{%0,%1,%2,%3}, {%4,%5,%6,%7}, {%8,%9}, {%0,%1,%2,%3};"
        : "+f"(c[0]), "+f"(c[1]), "+f"(c[2]), "+f"(c[3])
        : "r"(a[0]), "r"(a[1]), "r"(a[2]), "r"(a[3]), "r"(b[0]), "r"(b[1]));
}

__global__ __launch_bounds__(256, 1) void k_gemm(
    const __half* __restrict__ A, const __half* __restrict__ Bw,
    float* __restrict__ C) {
    extern __shared__ __half smh[];
    const uint32_t smb = smem_u32(smh);

    const int tid = threadIdx.x;
    const int wid = tid >> 5, lane = tid & 31;
    const int wm = wid & 1, wn = wid >> 1;       // 2(m) x 4(n)
    const int lr = lane >> 2, lc = lane & 3;
    const int m0 = blockIdx.x * GTM;
    const int n0 = blockIdx.y * GTN;

    float acc[4][8][4];
#pragma unroll
    for (int mf = 0; mf < 4; mf++)
#pragma unroll
        for (int nf = 0; nf < 8; nf++)
#pragma unroll
            for (int q = 0; q < 4; q++) acc[mf][nf][q] = 0.0f;

    // ldmatrix lane-address components (in halves, within a stage)
    // A tile mf: rows (wm*64 + mf*16 + (lane&15)), k offset ((lane>>4)*8)
    const uint32_t a_lane_off =
        (uint32_t)((wm * 64 + (lane & 15)) * ASTRH + ((lane >> 4) << 3));
    // B pair p: rows (wn*64 + p*16 + (lane&7) + ((lane>>4)&1)*8),
    //           k offset (((lane>>3)&1)*8)
    const uint32_t b_lane_off =
        (uint32_t)((wn * 64 + (lane & 7) + (((lane >> 4) & 1) << 3)) * ASTRH +
                   (((lane >> 3) & 1) << 3));

    // per-stage copy: rows have 8 chunks of 8 halves (16B).
    // A: 128 rows -> 1024 chunks (4/thread); B: 256 rows -> 2048 (8/thread)
    auto issue = [&](int kb, int s) {
        const uint32_t abase = smb + (uint32_t)(s * A_STAGE_H) * 2;
#pragma unroll
        for (int i = 0; i < 4; i++) {
            int j = tid + i * 256;
            int r = j >> 3, c8 = j & 7;
            cpasync16(abase + (uint32_t)(r * ASTRH + c8 * 8) * 2,
                      A + (size_t)(m0 + r) * DMODEL + kb * GKB + c8 * 8, 16);
        }
        const uint32_t bbase = smb + (uint32_t)(BOFFH + s * B_STAGE_H) * 2;
#pragma unroll
        for (int i = 0; i < 8; i++) {
            int j = tid + i * 256;
            int r = j >> 3, c8 = j & 7;
            int rn = n0 + r;
            int ok = (rn < VOCAB);
            int rsrc = ok ? rn : (VOCAB - 1);
            cpasync16(bbase + (uint32_t)(r * ASTRH + c8 * 8) * 2,
                      Bw + (size_t)rsrc * DMODEL + kb * GKB + c8 * 8, ok ? 16 : 0);
        }
        CP_COMMIT();
    };

    issue(0, 0);
    issue(1, 1);
    issue(2, 2);

    for (int kb = 0; kb < NKB; kb++) {
        const int s = kb % NSTAGE;
        if (kb + 3 < NKB) issue(kb + 3, (kb + 3) % NSTAGE); else CP_COMMIT();
        CP_WAIT3();        // 4 groups outstanding -> group kb complete
        __syncthreads();

        const uint32_t a_st = smb + (uint32_t)(s * A_STAGE_H + a_lane_off) * 2;
        const uint32_t b_st = smb + (uint32_t)(BOFFH + s * B_STAGE_H + b_lane_off) * 2;
#pragma unroll
        for (int sl = 0; sl < 4; sl++) {       // 4 x k16 slices
            const uint32_t ko = (uint32_t)(sl * 16) * 2;
            uint32_t af[4][4], bf[8][2];
#pragma unroll
            for (int mf = 0; mf < 4; mf++)
                ldsm_x4(af[mf], a_st + (uint32_t)(mf * 16 * ASTRH) * 2 + ko);
#pragma unroll
            for (int p = 0; p < 4; p++) {
                uint32_t r[4];
                ldsm_x4(r, b_st + (uint32_t)(p * 16 * ASTRH) * 2 + ko);
                bf[2 * p][0] = r[0]; bf[2 * p][1] = r[1];
                bf[2 * p + 1][0] = r[2]; bf[2 * p + 1][1] = r[3];
            }
#pragma unroll
            for (int mf = 0; mf < 4; mf++)
#pragma unroll
                for (int nf = 0; nf < 8; nf++)
                    mma_f16_16n8k16(acc[mf][nf], af[mf], bf[nf]);
        }
        __syncthreads();   // all warps done reading stage s
    }

    // epilogue: scalar 4B stores (VOCAB odd => no 8B alignment guarantee)
#pragma unroll
    for (int mf = 0; mf < 4; mf++) {
        const int row = m0 + wm * 64 + mf * 16 + lr;
#pragma unroll
        for (int nf = 0; nf < 8; nf++) {
            const int col = n0 + wn * 64 + nf * 8 + 2 * lc;
            float* c0p = C + (size_t)row * VOCAB + col;
            float* c2p = C + (size_t)(row + 8) * VOCAB + col;
            if (col + 1 < VOCAB) {
                c0p[0] = acc[mf][nf][0];
                c0p[1] = acc[mf][nf][1];
                c2p[0] = acc[mf][nf][2];
                c2p[1] = acc[mf][nf][3];
            } else if (col < VOCAB) {
                c0p[0] = acc[mf][nf][0];
                c2p[0] = acc[mf][nf][2];
            }
        }
    }
}

// ---------------------------------------------------------------------------
// Launch
// ---------------------------------------------------------------------------
extern "C" void kernel_launch(void* const* d_in, const int* in_sizes, int n_in,
                              void* d_out, int out_size) {
    const int*   idx   = (const int*)d_in[0];
    const float* Wemb  = (const float*)d_in[1];
    const float* G     = (const float*)d_in[2];
    const float* Win   = (const float*)d_in[3];
    const float* Wrec  = (const float*)d_in[4];
    const float* Wout  = (const float*)d_in[5];
    const float* gamma = (const float*)d_in[6];
    const float* beta  = (const float*)d_in[7];
    float* out = (float*)d_out;

    cudaFuncSetAttribute(k_gemm, cudaFuncAttributeMaxDynamicSharedMemorySize,
                         GEMM_SMEM);

    const size_t ng = ((size_t)VOCAB * DMODEL) / 8;
    k_round<<<(unsigned)((ng + 255) / 256), 256>>>(Wemb);
    k_embed_route<<<NROWS / 8, 160>>>(idx, Wemb, G, Win);
    k_scan<<<1, 128>>>(Wrec);
    k_outln<<<NROWS, 256>>>(Wout, gamma, beta);

    __half *hptr, *wtptr;
    cudaGetSymbolAddress((void**)&hptr, g_h16);
    cudaGetSymbolAddress((void**)&wtptr, g_Wh);
    dim3 grid(NROWS / GTM, (VOCAB + GTN - 1) / GTN);   // (16, 197)
    k_gemm<<<grid, 256, GEMM_SMEM>>>(hptr, wtptr, out);
}